// round 15
// baseline (speedup 1.0000x reference)
#include <cuda_runtime.h>
#include <cstdint>

#define BATCH_MAX 16384
#define XDIM 64
#define ADIM 16
#define NCON 8
#define N_ITERS 100
#define POW_ITERS 16
#define EPSC 0.05f   /* 1/(2*PEN) */

typedef unsigned long long ull;
#define FULLM 0xffffffffu

// ---------------- packed f32x2 helpers (sm_103a FFMA2) ----------------
__device__ __forceinline__ ull ffma2(ull a, ull b, ull c) {
    ull d;
    asm("fma.rn.f32x2 %0, %1, %2, %3;" : "=l"(d) : "l"(a), "l"(b), "l"(c));
    return d;
}
__device__ __forceinline__ float hadd2(ull p) {
    unsigned lo, hi;
    asm("mov.b64 {%0, %1}, %2;" : "=r"(lo), "=r"(hi) : "l"(p));
    return __uint_as_float(lo) + __uint_as_float(hi);
}

// ---------------- cp.async helpers ----------------
__device__ __forceinline__ void cp_async16(void* smem_ptr, const void* gptr) {
    uint32_t a = (uint32_t)__cvta_generic_to_shared(smem_ptr);
    asm volatile("cp.async.cg.shared.global [%0], [%1], 16;" :: "r"(a), "l"(gptr));
}
#define CP_COMMIT() asm volatile("cp.async.commit_group;")
#define CP_WAIT(n)  asm volatile("cp.async.wait_group %0;" :: "n"(n))

// ---------------- scratch (only Y remains) ----------------
__device__ float g_Y[BATCH_MAX * 512];

// =====================================================================
// Kernel 1: unchanged (43us; frozen).
// =====================================================================
#define K1_XS_BYTES  (16 * 129 * 16)
#define K1_WK_BYTES  (64 * 64 * 4)
#define K1_BUF_BYTES (32 * 129 * 4)
#define K1_SMEM (K1_XS_BYTES + K1_WK_BYTES + K1_BUF_BYTES)

__global__ __launch_bounds__(128) void k1_gemm(const float* __restrict__ X,
                                               const float* __restrict__ W)
{
    extern __shared__ char sm_raw[];
    float4 (*Xs4)[129] = (float4(*)[129])sm_raw;
    float  (*Wk)[64]   = (float(*)[64])(sm_raw + K1_XS_BYTES);
    float  (*buf)[129] = (float(*)[129])(sm_raw + K1_XS_BYTES + K1_WK_BYTES);

    const int t  = threadIdx.x;
    const int m0 = blockIdx.x * 128;
    const int n0 = blockIdx.y * 64;
    const int kq = t & 15, rg = t >> 4;

    const float4* X4 = (const float4*)X;
    const float4* W4 = (const float4*)W;
    #pragma unroll
    for (int it = 0; it < 16; it++) {
        int row = it * 8 + rg;
        Xs4[kq][row] = X4[(size_t)(m0 + row) * 16 + kq];
    }
    #pragma unroll
    for (int it = 0; it < 8; it++) {
        int n = it * 8 + rg;
        *(float4*)&Wk[n][kq * 4] = W4[(size_t)(n0 + n) * 16 + kq];
    }
    __syncthreads();

    const int lane = t & 31, w = t >> 5;
    const int m = w * 32 + lane;

    #pragma unroll 1
    for (int pass = 0; pass < 2; pass++) {
        ull acc2[32];
        #pragma unroll
        for (int n = 0; n < 32; n++) acc2[n] = 0ULL;

        const float (*Wp)[64] = Wk + pass * 32;
        #pragma unroll 4
        for (int kq2 = 0; kq2 < 16; kq2++) {
            ulonglong2 xq = *(const ulonglong2*)&Xs4[kq2][m];
            #pragma unroll
            for (int n = 0; n < 32; n++) {
                ulonglong2 wq = *(const ulonglong2*)&Wp[n][kq2 * 4];
                acc2[n] = ffma2(wq.x, xq.x, acc2[n]);
                acc2[n] = ffma2(wq.y, xq.y, acc2[n]);
            }
        }

        #pragma unroll
        for (int n = 0; n < 32; n++) buf[n][m] = hadd2(acc2[n]);
        __syncthreads();
        {
            int n4 = t & 7, mg = t >> 3;
            #pragma unroll
            for (int s = 0; s < 8; s++) {
                int mr = s * 16 + mg;
                float4 o = make_float4(buf[n4 * 4 + 0][mr], buf[n4 * 4 + 1][mr],
                                       buf[n4 * 4 + 2][mr], buf[n4 * 4 + 3][mr]);
                ((float4*)g_Y)[(size_t)(m0 + mr) * 128 + n0 / 4 + pass * 8 + n4] = o;
            }
        }
        __syncthreads();
    }
}

// =====================================================================
// Kernel 2 (FUSED, balanced): setup + per-warp FISTA.  Each warp runs
// the solver for ITS OWN element (4 replica groups of 8 lanes), so the
// tail is spread over all 4 SMSPs.  No __syncthreads before the tail —
// warps flow independently (per-warp smem slices only).
// =====================================================================
#define GS_STRIDE 68

__global__ __launch_bounds__(128) void k2_fused(
    const float* __restrict__ Xg, const float* __restrict__ Ag,
    const float* __restrict__ Bg, const float* __restrict__ ccg,
    const float* __restrict__ dcg, const float* __restrict__ adg,
    float* __restrict__ outg)
{
    __shared__ float xs [4][64];
    __shared__ float zs [4][64];
    __shared__ float gsm[4][NCON * GS_STRIDE];
    __shared__ float Bsm[4][1024];
    __shared__ float Lgs[4][128];
    __shared__ float ccs[512];
    __shared__ float Ssm[4][64];
    __shared__ float qsm[4][NCON];

    const int tid = threadIdx.x;
    const int w = tid >> 5, lane = tid & 31;
    const int b = blockIdx.x * 4 + w;

    for (int idx = tid; idx < 512; idx += 128) ccs[idx] = ccg[idx];

    if (lane < 16)
        *(float4*)&xs[w][lane * 4] = *(const float4*)(Xg + (size_t)b * 64 + lane * 4);

    {
        const float* Bb = Bg + (size_t)b * 1024;
        #pragma unroll
        for (int it = 0; it < 8; it++) {
            int idx = it * 128 + lane * 4;
            cp_async16(&Bsm[w][idx], Bb + idx);
        }
        const float* Yb = g_Y + (size_t)b * 512;
        #pragma unroll
        for (int it = 0; it < 4; it++) {
            int idx = it * 128 + lane * 4;
            int m = idx >> 6, i = idx & 63;
            cp_async16(&gsm[w][m * GS_STRIDE + i], Yb + idx);
        }
        CP_COMMIT();
    }

    // ---- z = A x: direct coalesced LDG, x in registers ----
    {
        const float4* A4 = (const float4*)(Ag + (size_t)b * 4096);
        float4 xv = *(const float4*)(Xg + (size_t)b * 64 + (lane & 15) * 4);
        const int rhalf = lane >> 4;
        #pragma unroll 2
        for (int g = 0; g < 8; g++) {
            float4 a[4];
            #pragma unroll
            for (int j = 0; j < 4; j++) a[j] = A4[(g * 4 + j) * 32 + lane];
            #pragma unroll
            for (int j = 0; j < 4; j++) {
                float part = fmaf(a[j].x, xv.x, a[j].y * xv.y);
                part = fmaf(a[j].z, xv.z, part);
                part = fmaf(a[j].w, xv.w, part);
                part += __shfl_xor_sync(FULLM, part, 1);
                part += __shfl_xor_sync(FULLM, part, 2);
                part += __shfl_xor_sync(FULLM, part, 4);
                part += __shfl_xor_sync(FULLM, part, 8);
                if ((lane & 15) == 0)
                    zs[w][(g * 4 + j) * 2 + rhalf] = part;
            }
        }
    }

    CP_WAIT(0);
    __syncwarp();   // warp-local: ccs/xs writes are from this warp's lanes
                    // for its own slice; ccs is block-shared but written
                    // before any cp.async wait — guard with a one-time
                    // block sync below only where ccs is consumed.
    // NOTE: ccs is written cooperatively by all 128 threads; the gradc
    // step below reads it.  One block-wide sync is still required for
    // ccs correctness — but it sits BEFORE the long tail, so tails still
    // overlap freely after it.
    __syncthreads();

    // ---- gradc = Y + cc in place ----
    {
        #pragma unroll
        for (int it = 0; it < 4; it++) {
            int idx = it * 128 + lane * 4;
            int m = idx >> 6, i = idx & 63;
            float4 yv = *(float4*)&gsm[w][m * GS_STRIDE + i];
            yv.x += ccs[idx + 0]; yv.y += ccs[idx + 1];
            yv.z += ccs[idx + 2]; yv.w += ccs[idx + 3];
            *(float4*)&gsm[w][m * GS_STRIDE + i] = yv;
        }
    }
    __syncwarp();

    float sa[NCON], sb[NCON], sc[NCON];
    {
        int i1 = lane, i2 = lane + 32;
        float x1 = xs[w][i1], x2 = xs[w][i2];
        float z1 = zs[w][i1], z2 = zs[w][i2];
        #pragma unroll
        for (int m = 0; m < NCON; m++) {
            float ga = gsm[w][m * GS_STRIDE + i1], gb2 = gsm[w][m * GS_STRIDE + i2];
            float ca = ccs[m * 64 + i1], cb = ccs[m * 64 + i2];
            sa[m] = fmaf(x2, gb2, x1 * ga);
            sb[m] = fmaf(x2, cb, x1 * ca);
            sc[m] = fmaf(z2, gb2, z1 * ga);
        }
    }
    #pragma unroll
    for (int off = 16; off; off >>= 1) {
        #pragma unroll
        for (int m = 0; m < NCON; m++) {
            sa[m] += __shfl_xor_sync(FULLM, sa[m], off);
            sb[m] += __shfl_xor_sync(FULLM, sb[m], off);
            sc[m] += __shfl_xor_sync(FULLM, sc[m], off);
        }
    }

    // Lg[m][a] = -sum_i gradc[m][i] * B[i][a]  -> Lgs (smem only)
    {
        int m = lane >> 2, aq = lane & 3;
        float4 acc = make_float4(0.f, 0.f, 0.f, 0.f);
        const float4* B4 = (const float4*)&Bsm[w][0];
        #pragma unroll
        for (int i = 0; i < 64; i++) {
            float gv = gsm[w][m * GS_STRIDE + i];
            float4 bv = B4[i * 4 + aq];
            acc.x = fmaf(gv, bv.x, acc.x);
            acc.y = fmaf(gv, bv.y, acc.y);
            acc.z = fmaf(gv, bv.z, acc.z);
            acc.w = fmaf(gv, bv.w, acc.w);
        }
        acc.x = -acc.x; acc.y = -acc.y; acc.z = -acc.z; acc.w = -acc.w;
        *(float4*)&Lgs[w][m * 16 + aq * 4] = acc;
    }
    __syncwarp();

    // q top -> qsm
    if (lane < NCON) {
        int m = lane;
        float g    = 0.5f * sa[m] + 0.5f * sb[m] - dcg[m];
        float bvec = sc[m] + g;
        float qm = bvec;
        const float* ad = adg + (size_t)b * 16;
        #pragma unroll
        for (int a = 0; a < 16; a++) qm = fmaf(-Lgs[w][m * 16 + a], ad[a], qm);
        qsm[w][m] = qm;
    }

    // S = 0.5 Lg Lg^T -> Ssm
    #pragma unroll
    for (int e = 0; e < 2; e++) {
        int idx = lane + e * 32;
        int r = idx >> 3, cI = idx & 7;
        float s = 0.f;
        #pragma unroll
        for (int a = 0; a < 16; a++) s = fmaf(Lgs[w][r * 16 + a], Lgs[w][cI * 16 + a], s);
        Ssm[w][idx] = 0.5f * s;
    }
    __syncwarp();   // warp-local staging complete; no block sync needed

    // ======== per-warp FISTA for OWN element: 4 replica groups of 8 ========
    const int r  = lane & 7;         // dual row 0..7
    const int gb = lane & ~7;        // 8-lane group base

    float S[8];
    {
        float4 s0 = *(const float4*)&Ssm[w][r * 8];
        float4 s1 = *(const float4*)&Ssm[w][r * 8 + 4];
        S[0]=s0.x; S[1]=s0.y; S[2]=s0.z; S[3]=s0.w;
        S[4]=s1.x; S[5]=s1.y; S[6]=s1.z; S[7]=s1.w;
    }
    const float qr = qsm[w][r];

    // ---- power iteration ----
    float v = 1.0f + 0.0625f * (float)r;
    #pragma unroll 1
    for (int it = 0; it < POW_ITERS; it++) {
        float ysv[8];
        #pragma unroll
        for (int j = 0; j < 8; j++) ysv[j] = __shfl_sync(FULLM, v, gb + j);
        float wv = 0.f;
        #pragma unroll
        for (int j = 0; j < 8; j++) wv = fmaf(S[j], ysv[j], wv);
        float ss = fmaf(wv, wv, 1e-30f);
        ss += __shfl_xor_sync(FULLM, ss, 1);
        ss += __shfl_xor_sync(FULLM, ss, 2);
        ss += __shfl_xor_sync(FULLM, ss, 4);
        v = wv * rsqrtf(ss);
    }
    float t;
    {
        float ysv[8];
        #pragma unroll
        for (int j = 0; j < 8; j++) ysv[j] = __shfl_sync(FULLM, v, gb + j);
        float wv = 0.f;
        #pragma unroll
        for (int j = 0; j < 8; j++) wv = fmaf(S[j], ysv[j], wv);
        float num = v * wv;
        float den = fmaf(v, v, 1e-30f);
        num += __shfl_xor_sync(FULLM, num, 1);
        num += __shfl_xor_sync(FULLM, num, 2);
        num += __shfl_xor_sync(FULLM, num, 4);
        den += __shfl_xor_sync(FULLM, den, 1);
        den += __shfl_xor_sync(FULLM, den, 2);
        den += __shfl_xor_sync(FULLM, den, 4);
        float mu = fmaxf(num / den, 0.f);
        float lamMax = EPSC + 0.5f * (mu + sqrtf(fmaf(mu, mu, 4.f * EPSC * EPSC)));
        t = 1.0f / (lamMax * 1.01f + 1e-6f);
    }

    // ---- FISTA ----
    float yt = 0.f, yb = 0.f, lt = 0.f, lb = 0.f;
    float tk = 1.0f;
    #pragma unroll 1
    for (int it = 0; it < N_ITERS; it++) {
        float ysv[8];
        #pragma unroll
        for (int j = 0; j < 8; j++) ysv[j] = __shfl_sync(FULLM, yt, gb + j);
        float wv = 0.f;
        #pragma unroll
        for (int j = 0; j < 8; j++) wv = fmaf(S[j], ysv[j], wv);
        float tk1  = 0.5f * (1.0f + sqrtf(fmaf(4.0f * tk, tk, 1.0f)));
        float beta = (tk - 1.0f) / tk1;

        float e0 = EPSC * (yt + yb);
        float g0 = wv + e0 - qr;
        float nt = fmaxf(fmaf(-t, g0, yt), 0.f);
        float nb = fmaxf(fmaf(-t, e0, yb), 0.f);
        yt = fmaf(beta, nt - lt, nt);
        yb = fmaf(beta, nb - lb, nb);
        lt = nt; lb = nb;
        tk = tk1;
    }

    // ---- primal: lanes 0..15 each produce one output column ----
    {
        float lam[8];
        #pragma unroll
        for (int j = 0; j < 8; j++) lam[j] = __shfl_sync(FULLM, lt, j);  // group 0's copy
        if (lane < 16) {
            float a = adg[(size_t)b * 16 + lane];
            #pragma unroll
            for (int m = 0; m < 8; m++)
                a = fmaf(0.5f * lam[m], Lgs[w][m * 16 + lane], a);
            outg[(size_t)b * 16 + lane] = a;
        }
    }
}

// =====================================================================
extern "C" void kernel_launch(void* const* d_in, const int* in_sizes, int n_in,
                              void* d_out, int out_size)
{
    const float* a_des = (const float*)d_in[0];
    const float* x     = (const float*)d_in[1];
    const float* A     = (const float*)d_in[2];
    const float* B     = (const float*)d_in[3];
    const float* Qc    = (const float*)d_in[4];
    const float* cc    = (const float*)d_in[5];
    const float* dc    = (const float*)d_in[6];
    const int batch = in_sizes[0] / ADIM;   // 16384

    cudaFuncSetAttribute(k1_gemm, cudaFuncAttributeMaxDynamicSharedMemorySize, K1_SMEM);

    dim3 g1(batch / 128, 512 / 64);
    k1_gemm<<<g1, 128, K1_SMEM>>>(x, Qc);
    k2_fused<<<batch / 4, 128>>>(x, A, B, cc, dc, a_des, (float*)d_out);
}

// round 16
// speedup vs baseline: 1.2448x; 1.2448x over previous
#include <cuda_runtime.h>
#include <cstdint>

#define BATCH_MAX 16384
#define XDIM 64
#define ADIM 16
#define NCON 8
#define N_ITERS 100
#define POW_ITERS 16
#define EPSC 0.05f   /* 1/(2*PEN) */

typedef unsigned long long ull;
#define FULLM 0xffffffffu

// ---------------- packed f32x2 helpers (sm_103a FFMA2) ----------------
__device__ __forceinline__ ull ffma2(ull a, ull b, ull c) {
    ull d;
    asm("fma.rn.f32x2 %0, %1, %2, %3;" : "=l"(d) : "l"(a), "l"(b), "l"(c));
    return d;
}
__device__ __forceinline__ float hadd2(ull p) {
    unsigned lo, hi;
    asm("mov.b64 {%0, %1}, %2;" : "=r"(lo), "=r"(hi) : "l"(p));
    return __uint_as_float(lo) + __uint_as_float(hi);
}

// ---------------- cp.async helpers ----------------
__device__ __forceinline__ void cp_async16(void* smem_ptr, const void* gptr) {
    uint32_t a = (uint32_t)__cvta_generic_to_shared(smem_ptr);
    asm volatile("cp.async.cg.shared.global [%0], [%1], 16;" :: "r"(a), "l"(gptr));
}
#define CP_COMMIT() asm volatile("cp.async.commit_group;")
#define CP_WAIT(n)  asm volatile("cp.async.wait_group %0;" :: "n"(n))

// ---------------- scratch ----------------
__device__ float g_Y [BATCH_MAX * 512];
__device__ float g_S [BATCH_MAX * 64];
__device__ float g_q [BATCH_MAX * 8];
__device__ float g_Lg[BATCH_MAX * 128];

// =====================================================================
// Kernel 1: R12 version, byte-identical (43us; frozen).
// =====================================================================
#define K1_XS_BYTES  (16 * 129 * 16)
#define K1_WK_BYTES  (64 * 64 * 4)
#define K1_BUF_BYTES (32 * 129 * 4)
#define K1_SMEM (K1_XS_BYTES + K1_WK_BYTES + K1_BUF_BYTES)

__global__ __launch_bounds__(128) void k1_gemm(const float* __restrict__ X,
                                               const float* __restrict__ W)
{
    extern __shared__ char sm_raw[];
    float4 (*Xs4)[129] = (float4(*)[129])sm_raw;
    float  (*Wk)[64]   = (float(*)[64])(sm_raw + K1_XS_BYTES);
    float  (*buf)[129] = (float(*)[129])(sm_raw + K1_XS_BYTES + K1_WK_BYTES);

    const int t  = threadIdx.x;
    const int m0 = blockIdx.x * 128;
    const int n0 = blockIdx.y * 64;
    const int kq = t & 15, rg = t >> 4;

    const float4* X4 = (const float4*)X;
    const float4* W4 = (const float4*)W;
    #pragma unroll
    for (int it = 0; it < 16; it++) {
        int row = it * 8 + rg;
        Xs4[kq][row] = X4[(size_t)(m0 + row) * 16 + kq];
    }
    #pragma unroll
    for (int it = 0; it < 8; it++) {
        int n = it * 8 + rg;
        *(float4*)&Wk[n][kq * 4] = W4[(size_t)(n0 + n) * 16 + kq];
    }
    __syncthreads();

    const int lane = t & 31, w = t >> 5;
    const int m = w * 32 + lane;

    #pragma unroll 1
    for (int pass = 0; pass < 2; pass++) {
        ull acc2[32];
        #pragma unroll
        for (int n = 0; n < 32; n++) acc2[n] = 0ULL;

        const float (*Wp)[64] = Wk + pass * 32;
        #pragma unroll 4
        for (int kq2 = 0; kq2 < 16; kq2++) {
            ulonglong2 xq = *(const ulonglong2*)&Xs4[kq2][m];
            #pragma unroll
            for (int n = 0; n < 32; n++) {
                ulonglong2 wq = *(const ulonglong2*)&Wp[n][kq2 * 4];
                acc2[n] = ffma2(wq.x, xq.x, acc2[n]);
                acc2[n] = ffma2(wq.y, xq.y, acc2[n]);
            }
        }

        #pragma unroll
        for (int n = 0; n < 32; n++) buf[n][m] = hadd2(acc2[n]);
        __syncthreads();
        {
            int n4 = t & 7, mg = t >> 3;
            #pragma unroll
            for (int s = 0; s < 8; s++) {
                int mr = s * 16 + mg;
                float4 o = make_float4(buf[n4 * 4 + 0][mr], buf[n4 * 4 + 1][mr],
                                       buf[n4 * 4 + 2][mr], buf[n4 * 4 + 3][mr]);
                ((float4*)g_Y)[(size_t)(m0 + mr) * 128 + n0 / 4 + pass * 8 + n4] = o;
            }
        }
        __syncthreads();
    }
}

// =====================================================================
// Kernel 2: R12 version, byte-identical (~86us).
// =====================================================================
#define GS_STRIDE 68

__global__ __launch_bounds__(128) void k2_setup(
    const float* __restrict__ Xg, const float* __restrict__ Ag,
    const float* __restrict__ Bg, const float* __restrict__ ccg,
    const float* __restrict__ dcg, const float* __restrict__ adg)
{
    __shared__ float xs [4][64];
    __shared__ float zs [4][64];
    __shared__ float gsm[4][NCON * GS_STRIDE];
    __shared__ float Bsm[4][1024];
    __shared__ float Lgs[4][128];
    __shared__ float ccs[512];

    const int tid = threadIdx.x;
    const int w = tid >> 5, lane = tid & 31;
    const int b = blockIdx.x * 4 + w;

    for (int idx = tid; idx < 512; idx += 128) ccs[idx] = ccg[idx];

    if (lane < 16)
        *(float4*)&xs[w][lane * 4] = *(const float4*)(Xg + (size_t)b * 64 + lane * 4);

    {
        const float* Bb = Bg + (size_t)b * 1024;
        #pragma unroll
        for (int it = 0; it < 8; it++) {
            int idx = it * 128 + lane * 4;
            cp_async16(&Bsm[w][idx], Bb + idx);
        }
        const float* Yb = g_Y + (size_t)b * 512;
        #pragma unroll
        for (int it = 0; it < 4; it++) {
            int idx = it * 128 + lane * 4;
            int m = idx >> 6, i = idx & 63;
            cp_async16(&gsm[w][m * GS_STRIDE + i], Yb + idx);
        }
        CP_COMMIT();
    }

    // ---- z = A x: direct coalesced LDG, x in registers ----
    {
        const float4* A4 = (const float4*)(Ag + (size_t)b * 4096);
        float4 xv = *(const float4*)(Xg + (size_t)b * 64 + (lane & 15) * 4);
        const int rhalf = lane >> 4;
        #pragma unroll 2
        for (int g = 0; g < 8; g++) {
            float4 a[4];
            #pragma unroll
            for (int j = 0; j < 4; j++) a[j] = A4[(g * 4 + j) * 32 + lane];
            #pragma unroll
            for (int j = 0; j < 4; j++) {
                float part = fmaf(a[j].x, xv.x, a[j].y * xv.y);
                part = fmaf(a[j].z, xv.z, part);
                part = fmaf(a[j].w, xv.w, part);
                part += __shfl_xor_sync(FULLM, part, 1);
                part += __shfl_xor_sync(FULLM, part, 2);
                part += __shfl_xor_sync(FULLM, part, 4);
                part += __shfl_xor_sync(FULLM, part, 8);
                if ((lane & 15) == 0)
                    zs[w][(g * 4 + j) * 2 + rhalf] = part;
            }
        }
    }

    CP_WAIT(0);
    __syncthreads();

    // ---- gradc = Y + cc in place ----
    {
        #pragma unroll
        for (int it = 0; it < 4; it++) {
            int idx = it * 128 + lane * 4;
            int m = idx >> 6, i = idx & 63;
            float4 yv = *(float4*)&gsm[w][m * GS_STRIDE + i];
            yv.x += ccs[idx + 0]; yv.y += ccs[idx + 1];
            yv.z += ccs[idx + 2]; yv.w += ccs[idx + 3];
            *(float4*)&gsm[w][m * GS_STRIDE + i] = yv;
        }
    }
    __syncwarp();

    float sa[NCON], sb[NCON], sc[NCON];
    {
        int i1 = lane, i2 = lane + 32;
        float x1 = xs[w][i1], x2 = xs[w][i2];
        float z1 = zs[w][i1], z2 = zs[w][i2];
        #pragma unroll
        for (int m = 0; m < NCON; m++) {
            float ga = gsm[w][m * GS_STRIDE + i1], gb2 = gsm[w][m * GS_STRIDE + i2];
            float ca = ccs[m * 64 + i1], cb = ccs[m * 64 + i2];
            sa[m] = fmaf(x2, gb2, x1 * ga);
            sb[m] = fmaf(x2, cb, x1 * ca);
            sc[m] = fmaf(z2, gb2, z1 * ga);
        }
    }
    #pragma unroll
    for (int off = 16; off; off >>= 1) {
        #pragma unroll
        for (int m = 0; m < NCON; m++) {
            sa[m] += __shfl_xor_sync(FULLM, sa[m], off);
            sb[m] += __shfl_xor_sync(FULLM, sb[m], off);
            sc[m] += __shfl_xor_sync(FULLM, sc[m], off);
        }
    }

    {
        int m = lane >> 2, aq = lane & 3;
        float4 acc = make_float4(0.f, 0.f, 0.f, 0.f);
        const float4* B4 = (const float4*)&Bsm[w][0];
        #pragma unroll
        for (int i = 0; i < 64; i++) {
            float gv = gsm[w][m * GS_STRIDE + i];
            float4 bv = B4[i * 4 + aq];
            acc.x = fmaf(gv, bv.x, acc.x);
            acc.y = fmaf(gv, bv.y, acc.y);
            acc.z = fmaf(gv, bv.z, acc.z);
            acc.w = fmaf(gv, bv.w, acc.w);
        }
        acc.x = -acc.x; acc.y = -acc.y; acc.z = -acc.z; acc.w = -acc.w;
        *(float4*)&Lgs[w][m * 16 + aq * 4] = acc;
        *(float4*)(g_Lg + (size_t)b * 128 + m * 16 + aq * 4) = acc;
    }
    __syncwarp();

    if (lane < NCON) {
        int m = lane;
        float g    = 0.5f * sa[m] + 0.5f * sb[m] - dcg[m];
        float bvec = sc[m] + g;
        float qm = bvec;
        const float* ad = adg + (size_t)b * 16;
        #pragma unroll
        for (int a = 0; a < 16; a++) qm = fmaf(-Lgs[w][m * 16 + a], ad[a], qm);
        g_q[(size_t)b * 8 + m] = qm;
    }

    #pragma unroll
    for (int e = 0; e < 2; e++) {
        int idx = lane + e * 32;
        int r = idx >> 3, cI = idx & 7;
        float s = 0.f;
        #pragma unroll
        for (int a = 0; a < 16; a++) s = fmaf(Lgs[w][r * 16 + a], Lgs[w][cI * 16 + a], s);
        g_S[(size_t)b * 64 + idx] = 0.5f * s;
    }
}

// =====================================================================
// Kernel 3 (redesigned): 8 lanes per element, 4 elements per warp.
// Combines R14's low instruction count with R15's SMSP balance.
// 131072 threads, 4096 warps; ~3.1K instrs/warp for the whole solve.
// =====================================================================
__global__ __launch_bounds__(128) void k3_fista(const float* __restrict__ adg,
                                                float* __restrict__ out, int batch)
{
    const int gwarp = (blockIdx.x * 128 + threadIdx.x) >> 5;
    const int lane  = threadIdx.x & 31;
    const int e     = lane >> 3;         // element within warp quartet
    const int r     = lane & 7;          // dual row
    const int gb    = lane & ~7;         // 8-lane group base
    const int b     = gwarp * 4 + e;
    if (b >= batch) return;

    // ---- load S row r (8 floats = 2 float4; warp covers 1KB contiguous) ----
    float S[8];
    {
        const float4* Sb = (const float4*)(g_S + (size_t)b * 64 + r * 8);
        float4 s0 = Sb[0], s1 = Sb[1];
        S[0]=s0.x; S[1]=s0.y; S[2]=s0.z; S[3]=s0.w;
        S[4]=s1.x; S[5]=s1.y; S[6]=s1.z; S[7]=s1.w;
    }
    const float qr = g_q[(size_t)b * 8 + r];

    // ---- power iteration ----
    float v = 1.0f + 0.0625f * (float)r;
    #pragma unroll 1
    for (int it = 0; it < POW_ITERS; it++) {
        float ysv[8];
        #pragma unroll
        for (int j = 0; j < 8; j++) ysv[j] = __shfl_sync(FULLM, v, gb + j);
        float wv = 0.f;
        #pragma unroll
        for (int j = 0; j < 8; j++) wv = fmaf(S[j], ysv[j], wv);
        float ss = fmaf(wv, wv, 1e-30f);
        ss += __shfl_xor_sync(FULLM, ss, 1);
        ss += __shfl_xor_sync(FULLM, ss, 2);
        ss += __shfl_xor_sync(FULLM, ss, 4);
        v = wv * rsqrtf(ss);
    }
    float t;
    {
        float ysv[8];
        #pragma unroll
        for (int j = 0; j < 8; j++) ysv[j] = __shfl_sync(FULLM, v, gb + j);
        float wv = 0.f;
        #pragma unroll
        for (int j = 0; j < 8; j++) wv = fmaf(S[j], ysv[j], wv);
        float num = v * wv;
        float den = fmaf(v, v, 1e-30f);
        num += __shfl_xor_sync(FULLM, num, 1);
        num += __shfl_xor_sync(FULLM, num, 2);
        num += __shfl_xor_sync(FULLM, num, 4);
        den += __shfl_xor_sync(FULLM, den, 1);
        den += __shfl_xor_sync(FULLM, den, 2);
        den += __shfl_xor_sync(FULLM, den, 4);
        float mu = fmaxf(num / den, 0.f);
        float lamMax = EPSC + 0.5f * (mu + sqrtf(fmaf(mu, mu, 4.f * EPSC * EPSC)));
        t = 1.0f / (lamMax * 1.01f + 1e-6f);
    }

    // ---- FISTA ----
    float yt = 0.f, yb = 0.f, lt = 0.f, lb = 0.f;
    float tk = 1.0f;
    #pragma unroll 1
    for (int it = 0; it < N_ITERS; it++) {
        float ysv[8];
        #pragma unroll
        for (int j = 0; j < 8; j++) ysv[j] = __shfl_sync(FULLM, yt, gb + j);
        float wv = 0.f;
        #pragma unroll
        for (int j = 0; j < 8; j++) wv = fmaf(S[j], ysv[j], wv);
        float tk1  = 0.5f * (1.0f + sqrtf(fmaf(4.0f * tk, tk, 1.0f)));
        float beta = (tk - 1.0f) / tk1;

        float e0 = EPSC * (yt + yb);
        float g0 = wv + e0 - qr;
        float nt = fmaxf(fmaf(-t, g0, yt), 0.f);
        float nb = fmaxf(fmaf(-t, e0, yb), 0.f);
        yt = fmaf(beta, nt - lt, nt);
        yb = fmaf(beta, nb - lb, nb);
        lt = nt; lb = nb;
        tk = tk1;
    }

    // ---- primal: each lane computes 2 output columns (2r, 2r+1) ----
    {
        float lam[8];
        #pragma unroll
        for (int j = 0; j < 8; j++) lam[j] = __shfl_sync(FULLM, lt, gb + j);
        const float* Lgb = g_Lg + (size_t)b * 128;
        float2 a = *(const float2*)(adg + (size_t)b * 16 + 2 * r);
        #pragma unroll
        for (int m = 0; m < 8; m++) {
            float lm = 0.5f * lam[m];
            float2 g2 = *(const float2*)(Lgb + m * 16 + 2 * r);
            a.x = fmaf(lm, g2.x, a.x);
            a.y = fmaf(lm, g2.y, a.y);
        }
        *(float2*)(out + (size_t)b * 16 + 2 * r) = a;
    }
}

// =====================================================================
extern "C" void kernel_launch(void* const* d_in, const int* in_sizes, int n_in,
                              void* d_out, int out_size)
{
    const float* a_des = (const float*)d_in[0];
    const float* x     = (const float*)d_in[1];
    const float* A     = (const float*)d_in[2];
    const float* B     = (const float*)d_in[3];
    const float* Qc    = (const float*)d_in[4];
    const float* cc    = (const float*)d_in[5];
    const float* dc    = (const float*)d_in[6];
    const int batch = in_sizes[0] / ADIM;   // 16384

    cudaFuncSetAttribute(k1_gemm, cudaFuncAttributeMaxDynamicSharedMemorySize, K1_SMEM);

    dim3 g1(batch / 128, 512 / 64);
    k1_gemm<<<g1, 128, K1_SMEM>>>(x, Qc);
    k2_setup<<<batch / 4, 128>>>(x, A, B, cc, dc, a_des);
    // 8 lanes/element, 4 elements/warp: batch*8 threads total
    k3_fista<<<(batch * 8 + 127) / 128, 128>>>(a_des, (float*)d_out, batch);
}

// round 17
// speedup vs baseline: 1.4255x; 1.1451x over previous
#include <cuda_runtime.h>
#include <cstdint>

#define BATCH_MAX 16384
#define XDIM 64
#define ADIM 16
#define NCON 8
#define N_ITERS 100
#define POW_ITERS 16
#define EPSC 0.05f   /* 1/(2*PEN) */

typedef unsigned long long ull;
#define FULLM 0xffffffffu

// ---------------- packed f32x2 helpers (sm_103a FFMA2) ----------------
__device__ __forceinline__ ull ffma2(ull a, ull b, ull c) {
    ull d;
    asm("fma.rn.f32x2 %0, %1, %2, %3;" : "=l"(d) : "l"(a), "l"(b), "l"(c));
    return d;
}
__device__ __forceinline__ float hadd2(ull p) {
    unsigned lo, hi;
    asm("mov.b64 {%0, %1}, %2;" : "=r"(lo), "=r"(hi) : "l"(p));
    return __uint_as_float(lo) + __uint_as_float(hi);
}
__device__ __forceinline__ ull pack2(float a, float b) {
    ull d;
    asm("mov.b64 %0, {%1, %2};" : "=l"(d)
        : "r"(__float_as_uint(a)), "r"(__float_as_uint(b)));
    return d;
}
__device__ __forceinline__ float dot8p(const ull* Sr, const ull* yp) {
    ull acc = ffma2(Sr[0], yp[0], 0ULL);
    acc = ffma2(Sr[1], yp[1], acc);
    acc = ffma2(Sr[2], yp[2], acc);
    acc = ffma2(Sr[3], yp[3], acc);
    return hadd2(acc);
}

// ---------------- cp.async helpers ----------------
__device__ __forceinline__ void cp_async16(void* smem_ptr, const void* gptr) {
    uint32_t a = (uint32_t)__cvta_generic_to_shared(smem_ptr);
    asm volatile("cp.async.cg.shared.global [%0], [%1], 16;" :: "r"(a), "l"(gptr));
}
#define CP_COMMIT() asm volatile("cp.async.commit_group;")
#define CP_WAIT(n)  asm volatile("cp.async.wait_group %0;" :: "n"(n))

// ---------------- scratch ----------------
__device__ float g_Y [BATCH_MAX * 512];
__device__ float g_S [BATCH_MAX * 64];
__device__ float g_q [BATCH_MAX * 8];
__device__ float g_Lg[BATCH_MAX * 128];

// =====================================================================
// Kernel 1: R12 version, byte-identical (43us; frozen).
// =====================================================================
#define K1_XS_BYTES  (16 * 129 * 16)
#define K1_WK_BYTES  (64 * 64 * 4)
#define K1_BUF_BYTES (32 * 129 * 4)
#define K1_SMEM (K1_XS_BYTES + K1_WK_BYTES + K1_BUF_BYTES)

__global__ __launch_bounds__(128) void k1_gemm(const float* __restrict__ X,
                                               const float* __restrict__ W)
{
    extern __shared__ char sm_raw[];
    float4 (*Xs4)[129] = (float4(*)[129])sm_raw;
    float  (*Wk)[64]   = (float(*)[64])(sm_raw + K1_XS_BYTES);
    float  (*buf)[129] = (float(*)[129])(sm_raw + K1_XS_BYTES + K1_WK_BYTES);

    const int t  = threadIdx.x;
    const int m0 = blockIdx.x * 128;
    const int n0 = blockIdx.y * 64;
    const int kq = t & 15, rg = t >> 4;

    const float4* X4 = (const float4*)X;
    const float4* W4 = (const float4*)W;
    #pragma unroll
    for (int it = 0; it < 16; it++) {
        int row = it * 8 + rg;
        Xs4[kq][row] = X4[(size_t)(m0 + row) * 16 + kq];
    }
    #pragma unroll
    for (int it = 0; it < 8; it++) {
        int n = it * 8 + rg;
        *(float4*)&Wk[n][kq * 4] = W4[(size_t)(n0 + n) * 16 + kq];
    }
    __syncthreads();

    const int lane = t & 31, w = t >> 5;
    const int m = w * 32 + lane;

    #pragma unroll 1
    for (int pass = 0; pass < 2; pass++) {
        ull acc2[32];
        #pragma unroll
        for (int n = 0; n < 32; n++) acc2[n] = 0ULL;

        const float (*Wp)[64] = Wk + pass * 32;
        #pragma unroll 4
        for (int kq2 = 0; kq2 < 16; kq2++) {
            ulonglong2 xq = *(const ulonglong2*)&Xs4[kq2][m];
            #pragma unroll
            for (int n = 0; n < 32; n++) {
                ulonglong2 wq = *(const ulonglong2*)&Wp[n][kq2 * 4];
                acc2[n] = ffma2(wq.x, xq.x, acc2[n]);
                acc2[n] = ffma2(wq.y, xq.y, acc2[n]);
            }
        }

        #pragma unroll
        for (int n = 0; n < 32; n++) buf[n][m] = hadd2(acc2[n]);
        __syncthreads();
        {
            int n4 = t & 7, mg = t >> 3;
            #pragma unroll
            for (int s = 0; s < 8; s++) {
                int mr = s * 16 + mg;
                float4 o = make_float4(buf[n4 * 4 + 0][mr], buf[n4 * 4 + 1][mr],
                                       buf[n4 * 4 + 2][mr], buf[n4 * 4 + 3][mr]);
                ((float4*)g_Y)[(size_t)(m0 + mr) * 128 + n0 / 4 + pass * 8 + n4] = o;
            }
        }
        __syncthreads();
    }
}

// =====================================================================
// Kernel 2: z=Ax with MLP=16 (2 passes of 16 independent LDG.128).
// launch_bounds(128,5) -> 102 regs available (64 data + state, no spill).
// Everything else identical to R12's k2.
// =====================================================================
#define GS_STRIDE 68

__global__ __launch_bounds__(128, 5) void k2_setup(
    const float* __restrict__ Xg, const float* __restrict__ Ag,
    const float* __restrict__ Bg, const float* __restrict__ ccg,
    const float* __restrict__ dcg, const float* __restrict__ adg)
{
    __shared__ float xs [4][64];
    __shared__ float zs [4][64];
    __shared__ float gsm[4][NCON * GS_STRIDE];
    __shared__ float Bsm[4][1024];
    __shared__ float Lgs[4][128];
    __shared__ float ccs[512];

    const int tid = threadIdx.x;
    const int w = tid >> 5, lane = tid & 31;
    const int b = blockIdx.x * 4 + w;

    for (int idx = tid; idx < 512; idx += 128) ccs[idx] = ccg[idx];

    if (lane < 16)
        *(float4*)&xs[w][lane * 4] = *(const float4*)(Xg + (size_t)b * 64 + lane * 4);

    {
        const float* Bb = Bg + (size_t)b * 1024;
        #pragma unroll
        for (int it = 0; it < 8; it++) {
            int idx = it * 128 + lane * 4;
            cp_async16(&Bsm[w][idx], Bb + idx);
        }
        const float* Yb = g_Y + (size_t)b * 512;
        #pragma unroll
        for (int it = 0; it < 4; it++) {
            int idx = it * 128 + lane * 4;
            int m = idx >> 6, i = idx & 63;
            cp_async16(&gsm[w][m * GS_STRIDE + i], Yb + idx);
        }
        CP_COMMIT();
    }

    // ---- z = A x: 2 passes, 16 independent LDG.128 in flight per pass ----
    {
        const float4* A4 = (const float4*)(Ag + (size_t)b * 4096);
        float4 xv = *(const float4*)(Xg + (size_t)b * 64 + (lane & 15) * 4);
        const int rhalf = lane >> 4;
        #pragma unroll 1
        for (int pass = 0; pass < 2; pass++) {
            const float4* Ap = A4 + pass * 512;
            float4 a[16];
            #pragma unroll
            for (int j = 0; j < 16; j++) a[j] = Ap[j * 32 + lane];
            #pragma unroll
            for (int j = 0; j < 16; j++) {
                float part = fmaf(a[j].x, xv.x, a[j].y * xv.y);
                part = fmaf(a[j].z, xv.z, part);
                part = fmaf(a[j].w, xv.w, part);
                part += __shfl_xor_sync(FULLM, part, 1);
                part += __shfl_xor_sync(FULLM, part, 2);
                part += __shfl_xor_sync(FULLM, part, 4);
                part += __shfl_xor_sync(FULLM, part, 8);
                if ((lane & 15) == 0)
                    zs[w][pass * 32 + j * 2 + rhalf] = part;
            }
        }
    }

    CP_WAIT(0);
    __syncthreads();

    // ---- gradc = Y + cc in place ----
    {
        #pragma unroll
        for (int it = 0; it < 4; it++) {
            int idx = it * 128 + lane * 4;
            int m = idx >> 6, i = idx & 63;
            float4 yv = *(float4*)&gsm[w][m * GS_STRIDE + i];
            yv.x += ccs[idx + 0]; yv.y += ccs[idx + 1];
            yv.z += ccs[idx + 2]; yv.w += ccs[idx + 3];
            *(float4*)&gsm[w][m * GS_STRIDE + i] = yv;
        }
    }
    __syncwarp();

    float sa[NCON], sb[NCON], sc[NCON];
    {
        int i1 = lane, i2 = lane + 32;
        float x1 = xs[w][i1], x2 = xs[w][i2];
        float z1 = zs[w][i1], z2 = zs[w][i2];
        #pragma unroll
        for (int m = 0; m < NCON; m++) {
            float ga = gsm[w][m * GS_STRIDE + i1], gb2 = gsm[w][m * GS_STRIDE + i2];
            float ca = ccs[m * 64 + i1], cb = ccs[m * 64 + i2];
            sa[m] = fmaf(x2, gb2, x1 * ga);
            sb[m] = fmaf(x2, cb, x1 * ca);
            sc[m] = fmaf(z2, gb2, z1 * ga);
        }
    }
    #pragma unroll
    for (int off = 16; off; off >>= 1) {
        #pragma unroll
        for (int m = 0; m < NCON; m++) {
            sa[m] += __shfl_xor_sync(FULLM, sa[m], off);
            sb[m] += __shfl_xor_sync(FULLM, sb[m], off);
            sc[m] += __shfl_xor_sync(FULLM, sc[m], off);
        }
    }

    {
        int m = lane >> 2, aq = lane & 3;
        float4 acc = make_float4(0.f, 0.f, 0.f, 0.f);
        const float4* B4 = (const float4*)&Bsm[w][0];
        #pragma unroll
        for (int i = 0; i < 64; i++) {
            float gv = gsm[w][m * GS_STRIDE + i];
            float4 bv = B4[i * 4 + aq];
            acc.x = fmaf(gv, bv.x, acc.x);
            acc.y = fmaf(gv, bv.y, acc.y);
            acc.z = fmaf(gv, bv.z, acc.z);
            acc.w = fmaf(gv, bv.w, acc.w);
        }
        acc.x = -acc.x; acc.y = -acc.y; acc.z = -acc.z; acc.w = -acc.w;
        *(float4*)&Lgs[w][m * 16 + aq * 4] = acc;
        *(float4*)(g_Lg + (size_t)b * 128 + m * 16 + aq * 4) = acc;
    }
    __syncwarp();

    if (lane < NCON) {
        int m = lane;
        float g    = 0.5f * sa[m] + 0.5f * sb[m] - dcg[m];
        float bvec = sc[m] + g;
        float qm = bvec;
        const float* ad = adg + (size_t)b * 16;
        #pragma unroll
        for (int a = 0; a < 16; a++) qm = fmaf(-Lgs[w][m * 16 + a], ad[a], qm);
        g_q[(size_t)b * 8 + m] = qm;
    }

    #pragma unroll
    for (int e = 0; e < 2; e++) {
        int idx = lane + e * 32;
        int r = idx >> 3, cI = idx & 7;
        float s = 0.f;
        #pragma unroll
        for (int a = 0; a < 16; a++) s = fmaf(Lgs[w][r * 16 + a], Lgs[w][cI * 16 + a], s);
        g_S[(size_t)b * 64 + idx] = 0.5f * s;
    }
}

// =====================================================================
// Kernel 3: R12 quad version, byte-identical (30us measured; 8 elems/warp).
// =====================================================================
#define GATHER8(dst, v0, v1, qb)                            \
    do {                                                    \
        _Pragma("unroll")                                   \
        for (int s_ = 0; s_ < 4; s_++) {                    \
            dst[2*s_]   = __shfl_sync(FULLM, (v0), (qb)+s_);\
            dst[2*s_+1] = __shfl_sync(FULLM, (v1), (qb)+s_);\
        }                                                   \
    } while (0)

__global__ __launch_bounds__(128) void k3_fista(const float* __restrict__ adg,
                                                float* __restrict__ out, int batch)
{
    const int gtid = blockIdx.x * 128 + threadIdx.x;
    const int b    = gtid >> 2;
    const int sub  = gtid & 3;
    if (b >= batch) return;

    const int lane  = threadIdx.x & 31;
    const int qbase = lane & ~3;

    float S0[8], S1[8];
    {
        const float4* Sb = (const float4*)(g_S + (size_t)b * 64);
        float4 a0 = Sb[(2 * sub) * 2],     a1 = Sb[(2 * sub) * 2 + 1];
        float4 c0 = Sb[(2 * sub + 1) * 2], c1 = Sb[(2 * sub + 1) * 2 + 1];
        S0[0]=a0.x; S0[1]=a0.y; S0[2]=a0.z; S0[3]=a0.w;
        S0[4]=a1.x; S0[5]=a1.y; S0[6]=a1.z; S0[7]=a1.w;
        S1[0]=c0.x; S1[1]=c0.y; S1[2]=c0.z; S1[3]=c0.w;
        S1[4]=c1.x; S1[5]=c1.y; S1[6]=c1.z; S1[7]=c1.w;
    }
    const float2 qv = *(const float2*)(g_q + (size_t)b * 8 + 2 * sub);

    float v0 = 1.0f + 0.0625f * (float)(2 * sub);
    float v1 = 1.0f + 0.0625f * (float)(2 * sub + 1);
    #pragma unroll 1
    for (int it = 0; it < POW_ITERS; it++) {
        float ysv[8];
        GATHER8(ysv, v0, v1, qbase);
        float w0 = 0.f, w1 = 0.f;
        #pragma unroll
        for (int j = 0; j < 8; j++) {
            w0 = fmaf(S0[j], ysv[j], w0);
            w1 = fmaf(S1[j], ysv[j], w1);
        }
        float ss = fmaf(w0, w0, fmaf(w1, w1, 1e-30f));
        ss += __shfl_xor_sync(FULLM, ss, 1);
        ss += __shfl_xor_sync(FULLM, ss, 2);
        float inv = rsqrtf(ss);
        v0 = w0 * inv; v1 = w1 * inv;
    }
    float t;
    {
        float ysv[8];
        GATHER8(ysv, v0, v1, qbase);
        float w0 = 0.f, w1 = 0.f;
        #pragma unroll
        for (int j = 0; j < 8; j++) {
            w0 = fmaf(S0[j], ysv[j], w0);
            w1 = fmaf(S1[j], ysv[j], w1);
        }
        float num = fmaf(v0, w0, v1 * w1);
        float den = fmaf(v0, v0, fmaf(v1, v1, 1e-30f));
        num += __shfl_xor_sync(FULLM, num, 1);
        num += __shfl_xor_sync(FULLM, num, 2);
        den += __shfl_xor_sync(FULLM, den, 1);
        den += __shfl_xor_sync(FULLM, den, 2);
        float mu = fmaxf(num / den, 0.f);
        float lamMax = EPSC + 0.5f * (mu + sqrtf(fmaf(mu, mu, 4.f * EPSC * EPSC)));
        float L = lamMax * 1.01f + 1e-6f;
        t = 1.0f / L;
    }

    float yt0 = 0.f, yt1 = 0.f, yb0 = 0.f, yb1 = 0.f;
    float lt0 = 0.f, lt1 = 0.f, lb0 = 0.f, lb1 = 0.f;
    float tk = 1.0f;
    #pragma unroll 1
    for (int it = 0; it < N_ITERS; it++) {
        float ysv[8];
        GATHER8(ysv, yt0, yt1, qbase);
        float w0 = 0.f, w1 = 0.f;
        #pragma unroll
        for (int j = 0; j < 8; j++) {
            w0 = fmaf(S0[j], ysv[j], w0);
            w1 = fmaf(S1[j], ysv[j], w1);
        }
        float tk1  = 0.5f * (1.0f + sqrtf(fmaf(4.0f * tk, tk, 1.0f)));
        float beta = (tk - 1.0f) / tk1;

        float e0  = EPSC * (yt0 + yb0);
        float g0  = w0 + e0 - qv.x;
        float nt0 = fmaxf(fmaf(-t, g0, yt0), 0.f);
        float nb0 = fmaxf(fmaf(-t, e0, yb0), 0.f);
        yt0 = fmaf(beta, nt0 - lt0, nt0);
        yb0 = fmaf(beta, nb0 - lb0, nb0);
        lt0 = nt0; lb0 = nb0;

        float e1  = EPSC * (yt1 + yb1);
        float g1  = w1 + e1 - qv.y;
        float nt1 = fmaxf(fmaf(-t, g1, yt1), 0.f);
        float nb1 = fmaxf(fmaf(-t, e1, yb1), 0.f);
        yt1 = fmaf(beta, nt1 - lt1, nt1);
        yb1 = fmaf(beta, nb1 - lb1, nb1);
        lt1 = nt1; lb1 = nb1;

        tk = tk1;
    }

    {
        float lt[8];
        GATHER8(lt, lt0, lt1, qbase);
        const float4* Lg4 = (const float4*)(g_Lg + (size_t)b * 128);
        float4 a = ((const float4*)(adg + (size_t)b * 16))[sub];
        #pragma unroll
        for (int m = 0; m < 8; m++) {
            float lm = 0.5f * lt[m];
            float4 g = Lg4[m * 4 + sub];
            a.x = fmaf(lm, g.x, a.x);
            a.y = fmaf(lm, g.y, a.y);
            a.z = fmaf(lm, g.z, a.z);
            a.w = fmaf(lm, g.w, a.w);
        }
        ((float4*)out)[(size_t)b * 4 + sub] = a;
    }
}

// =====================================================================
extern "C" void kernel_launch(void* const* d_in, const int* in_sizes, int n_in,
                              void* d_out, int out_size)
{
    const float* a_des = (const float*)d_in[0];
    const float* x     = (const float*)d_in[1];
    const float* A     = (const float*)d_in[2];
    const float* B     = (const float*)d_in[3];
    const float* Qc    = (const float*)d_in[4];
    const float* cc    = (const float*)d_in[5];
    const float* dc    = (const float*)d_in[6];
    const int batch = in_sizes[0] / ADIM;   // 16384

    cudaFuncSetAttribute(k1_gemm, cudaFuncAttributeMaxDynamicSharedMemorySize, K1_SMEM);

    dim3 g1(batch / 128, 512 / 64);
    k1_gemm<<<g1, 128, K1_SMEM>>>(x, Qc);
    k2_setup<<<batch / 4, 128>>>(x, A, B, cc, dc, a_des);
    k3_fista<<<(batch * 4 + 127) / 128, 128>>>(a_des, (float*)d_out, batch);
}